// round 17
// baseline (speedup 1.0000x reference)
#include <cuda_runtime.h>
#include <cuda.h>
#include <cuda_fp16.h>
#include <math.h>

// ---------------------------------------------------------------------------
// HashGridT: Instant-NGP 2D multires hash encoding + temporal interpolation
//
//   K1: blend the two time slices into one device-global fp16 table (512 KB).
//   K2: level-pair CTA (R13: 32B TMA rows), two 512-thread pipelines (R14),
//       and R16/R17: FULL fp16 BILINEAR LERP. The gathered values are already
//       fp16; doing x/y-lerp with HSUB2/HFMA2 on half2 and converting only
//       the final result removes ~16 CVT + ~24 fp32 ops per point-level
//       (~19% of total issue; fma+alu carried 37% in R15's ncu).
//       Error audit: table grid quantum 2^-24; hsub2 exact on-grid, each
//       hfma2 <= 3e-8 abs -> norm rel_err ~4.7e-4, still 2x under gate.
//       smem: 128KB table + 2 x 3 x 16KB staging = 224 KB, 1 CTA/SM,
//       grid (37 x 4 pairs) = 148 CTAs = one wave.
//   (R17 = resubmission of R16: the R16 bench died to a broker infra
//    failure before producing any measurement.)
// ---------------------------------------------------------------------------

#define N_LEVELS     8
#define HASHMAP_SIZE 8192
#define HASH_MASK    8191u
#define PRIME_Y      2654435761u
#define TIME_RES     25
#define THREADS      1024
#define HALF         512             // threads per pipeline
#define HTILE        512             // points per half-tile (1 per thread)
#define NBUF         3               // staging buffers per half (wait_group 2)
#define BOX_ROWS     256             // TMA box: (8 floats, 1 pair, 256 points)

struct __align__(8) H4 { __half2 lo, hi; };

// Blended fp16 table: [level][hash] 4 feats. 512 KB static device global.
__device__ H4 g_btable_h[N_LEVELS * HASHMAP_SIZE];

// ---------------------------------------------------------------------------
// Kernel 1: temporal blend of the hash table (fp32 math, one fp16 round).
// ---------------------------------------------------------------------------
__global__ void blend_table_kernel(const float* __restrict__ table,
                                   const float* __restrict__ t_ptr) {
    int i = blockIdx.x * blockDim.x + threadIdx.x;  // 0 .. 65535

    float t   = *t_ptr;
    float idx = t * (float)(TIME_RES - 1);
    float fi1 = floorf(idx);
    float fi2 = ceilf(idx);
    int i1 = min(max((int)fi1, 0), TIME_RES - 1);
    int i2 = min(max((int)fi2, 0), TIME_RES - 1);
    float w2 = idx - fi1;
    float w1 = 1.0f - w2;

    const float4* tab = (const float4*)table;
    float4 a = tab[(size_t)i1 * (N_LEVELS * HASHMAP_SIZE) + i];
    float4 b = tab[(size_t)i2 * (N_LEVELS * HASHMAP_SIZE) + i];

    H4 h;
    h.lo = __floats2half2_rn(w1 * a.x + w2 * b.x, w1 * a.y + w2 * b.y);
    h.hi = __floats2half2_rn(w1 * a.z + w2 * b.z, w1 * a.w + w2 * b.w);
    g_btable_h[i] = h;
}

// ---------------------------------------------------------------------------
// Index + weight computation for one level (fp32, matches numpy rounding).
// ---------------------------------------------------------------------------
__device__ __forceinline__ void level_coords(float xc, float yc, float scale,
                                             unsigned& h00, unsigned& h10,
                                             unsigned& h01, unsigned& h11,
                                             float& wx, float& wy) {
    float px = __fadd_rn(__fmul_rn(xc, scale), 0.5f);
    float py = __fadd_rn(__fmul_rn(yc, scale), 0.5f);
    float fx = floorf(px);
    float fy = floorf(py);
    wx = px - fx;
    wy = py - fy;

    unsigned ix = (unsigned)(int)fx;
    unsigned iy = (unsigned)(int)fy;
    unsigned hy0 = iy * PRIME_Y;
    unsigned hy1 = hy0 + PRIME_Y;     // (iy+1)*PRIME_Y mod 2^32

    h00 = (ix        ^ hy0) & HASH_MASK;
    h10 = ((ix + 1u) ^ hy0) & HASH_MASK;
    h01 = (ix        ^ hy1) & HASH_MASK;
    h11 = ((ix + 1u) ^ hy1) & HASH_MASK;
}

// fp16 bilinear lerp of 4 gathered corners; returns fp32 result.
__device__ __forceinline__ float4 lerp_h(H4 q00, H4 q10, H4 q01, H4 q11,
                                         float wx, float wy) {
    __half2 wx2 = __float2half2_rn(wx);
    __half2 wy2 = __float2half2_rn(wy);
    __half2 alo = __hfma2(wx2, __hsub2(q10.lo, q00.lo), q00.lo);
    __half2 ahi = __hfma2(wx2, __hsub2(q10.hi, q00.hi), q00.hi);
    __half2 blo = __hfma2(wx2, __hsub2(q11.lo, q01.lo), q01.lo);
    __half2 bhi = __hfma2(wx2, __hsub2(q11.hi, q01.hi), q01.hi);
    __half2 rlo = __hfma2(wy2, __hsub2(blo, alo), alo);
    __half2 rhi = __hfma2(wy2, __hsub2(bhi, ahi), ahi);
    float2 rl = __half22float2(rlo);
    float2 rh = __half22float2(rhi);
    return make_float4(rl.x, rl.y, rh.x, rh.y);
}

// Both levels fused: all 8 LDS.64 issued before any arithmetic (gather MLP).
__device__ __forceinline__ void encode_pair(const H4* __restrict__ t0,
                                            const H4* __restrict__ t1,
                                            float xc, float yc,
                                            float s0, float s1,
                                            float4& r0, float4& r1) {
    unsigned a00, a10, a01, a11, b00, b10, b01, b11;
    float wx0, wy0, wx1, wy1;
    level_coords(xc, yc, s0, a00, a10, a01, a11, wx0, wy0);
    level_coords(xc, yc, s1, b00, b10, b01, b11, wx1, wy1);

    H4 qa00 = t0[a00];
    H4 qa10 = t0[a10];
    H4 qa01 = t0[a01];
    H4 qa11 = t0[a11];
    H4 qb00 = t1[b00];
    H4 qb10 = t1[b10];
    H4 qb01 = t1[b01];
    H4 qb11 = t1[b11];

    r0 = lerp_h(qa00, qa10, qa01, qa11, wx0, wy0);
    r1 = lerp_h(qb00, qb10, qb01, qb11, wx1, wy1);
}

__device__ __forceinline__ uint32_t smem_u32(const void* p) {
    return (uint32_t)__cvta_generic_to_shared(p);
}

#define BAR_SYNC(id) \
    asm volatile("bar.sync %0, %1;" :: "r"(id), "n"(HALF) : "memory")

// ---------------------------------------------------------------------------
// Kernel 2: level-pair encode, two independent 512-thread pipelines.
// smem: [0,128KB) fp16 tables (2 levels), then 2 x (3 x 16KB) staging.
// ---------------------------------------------------------------------------
__global__ void __launch_bounds__(THREADS, 1)
hash_encode_pair_kernel(const float2* __restrict__ x,
                        float4* __restrict__ out,     // tail fallback only
                        int N,
                        const __grid_constant__ CUtensorMap tmap)
{
    extern __shared__ char smem_raw[];
    H4*     s_tab = (H4*)smem_raw;                               // 2*8192
    float4* s_buf = (float4*)(smem_raw + 2 * HASHMAP_SIZE * 8);

    const int pair = blockIdx.y;        // levels 2*pair, 2*pair+1
    const int tid  = threadIdx.x;
    const int h    = tid >> 9;          // pipeline half: 0 or 1
    const int ltid = tid & (HALF - 1);
    const int bar  = 1 + h;             // named barrier id for this half

    // Stage BOTH levels' blended fp16 tables into SMEM (coalesced 8B).
    const H4* lt = g_btable_h + (2 * pair) * HASHMAP_SIZE;
    #pragma unroll
    for (int i = tid; i < 2 * HASHMAP_SIZE; i += THREADS)
        s_tab[i] = lt[i];
    __syncthreads();   // the ONLY CTA-wide barrier

    // Per-level scales, matching numpy float64 exp2 path then fp32 cast.
    const float scale0 =
        (float)(exp2((double)(2 * pair)     * (6.0 / 7.0)) * 512.0 - 1.0);
    const float scale1 =
        (float)(exp2((double)(2 * pair + 1) * (6.0 / 7.0)) * 512.0 - 1.0);

    // This half's private staging: NBUF buffers of HTILE rows x 32B.
    float4* hbuf = s_buf + h * (NBUF * HTILE * 2);

    const int n_tiles = (N + 2 * HTILE - 1) / (2 * HTILE);  // 1024-pt tiles
    const int stride  = gridDim.x;

    // Software pipeline: preload first half-tile's coordinate.
    int t = blockIdx.x;
    float2 c;
    if (t < n_tiles) {
        const int base = t * (2 * HTILE) + h * HTILE;
        if (base + ltid < N) c = __ldg(&x[base + ltid]);
    }

    int it = 0;
    for (; t < n_tiles; t += stride, ++it) {
        const int base = t * (2 * HTILE) + h * HTILE;
        const int rows = max(0, min(HTILE, N - base));
        const int full = rows & ~(BOX_ROWS - 1);

        // Prefetch next half-tile's x -- hides under this tile's compute.
        const int tn = t + stride;
        float2 cn;
        if (tn < n_tiles) {
            const int nb = tn * (2 * HTILE) + h * HTILE;
            if (nb + ltid < N) cn = __ldg(&x[nb + ltid]);
        }

        // Reuse guard: buffer (it % NBUF) was handed to TMA at it-NBUF;
        // allow at most NBUF-1 pending groups. Per-half leader only.
        if (ltid == 0)
            asm volatile("cp.async.bulk.wait_group 2;" ::: "memory");
        BAR_SYNC(bar);

        float4* buf = hbuf + (it % NBUF) * (HTILE * 2);

        if (ltid < rows) {
            float4 r0, r1;
            encode_pair(s_tab, s_tab + HASHMAP_SIZE,
                        c.x, c.y, scale0, scale1, r0, r1);
            if (ltid < full) {
                buf[ltid * 2]     = r0;   // 32B contiguous per point
                buf[ltid * 2 + 1] = r1;
            } else {
                size_t o = (size_t)(base + ltid) * N_LEVELS + 2 * pair;
                out[o]     = r0;
                out[o + 1] = r1;
            }
        }

        // Order generic-proxy STS before async-proxy TMA reads.
        asm volatile("fence.proxy.async;" ::: "memory");
        BAR_SYNC(bar);

        if (ltid == 0) {
            const int nb = full / BOX_ROWS;
            const uint32_t sa = smem_u32(buf);
            for (int j = 0; j < nb; ++j) {
                asm volatile(
                    "cp.async.bulk.tensor.3d.global.shared::cta.tile.bulk_group"
                    " [%0, {%1, %2, %3}], [%4];"
                    :: "l"(&tmap), "r"(0), "r"(pair), "r"(base + j * BOX_ROWS),
                       "r"(sa + (uint32_t)j * BOX_ROWS * 32u)
                    : "memory");
            }
            asm volatile("cp.async.bulk.commit_group;" ::: "memory");
        }

        c = cn;
    }

    // Drain this half's pending TMA stores before exit.
    if (ltid == 0)
        asm volatile("cp.async.bulk.wait_group 0;" ::: "memory");
    BAR_SYNC(bar);
}

// ---------------------------------------------------------------------------
// Kernel 2 (legacy STG fallback) -- used only if tensormap creation fails.
// ---------------------------------------------------------------------------
__global__ void __launch_bounds__(1024, 1)
hash_encode_kernel(const float2* __restrict__ x, float4* __restrict__ out, int N)
{
    extern __shared__ char smem_raw[];
    H4* s_tab = (H4*)smem_raw;
    const int pair = blockIdx.y;
    const H4* lt = g_btable_h + (2 * pair) * HASHMAP_SIZE;
    #pragma unroll
    for (int i = threadIdx.x; i < 2 * HASHMAP_SIZE; i += 1024)
        s_tab[i] = lt[i];
    __syncthreads();

    const float scale0 =
        (float)(exp2((double)(2 * pair)     * (6.0 / 7.0)) * 512.0 - 1.0);
    const float scale1 =
        (float)(exp2((double)(2 * pair + 1) * (6.0 / 7.0)) * 512.0 - 1.0);

    const int chunk = (N + gridDim.x - 1) / gridDim.x;
    const int n0 = blockIdx.x * chunk;
    const int n1 = min(n0 + chunk, N);

    for (int n = n0 + threadIdx.x; n < n1; n += 1024) {
        float2 p = __ldg(&x[n]);
        float4 r0, r1;
        encode_pair(s_tab, s_tab + HASHMAP_SIZE,
                    p.x, p.y, scale0, scale1, r0, r1);
        size_t o = (size_t)n * N_LEVELS + 2 * pair;
        out[o]     = r0;
        out[o + 1] = r1;
    }
}

// ---------------------------------------------------------------------------
// Host: tensormap encode via driver entry point (cudart-only lookup).
// ---------------------------------------------------------------------------
typedef CUresult (*EncodeTiledFn)(
    CUtensorMap*, CUtensorMapDataType, cuuint32_t, void*,
    const cuuint64_t*, const cuuint64_t*, const cuuint32_t*, const cuuint32_t*,
    CUtensorMapInterleave, CUtensorMapSwizzle, CUtensorMapL2promotion,
    CUtensorMapFloatOOBfill);

static EncodeTiledFn get_encode_fn() {
    void* p = nullptr;
#if CUDART_VERSION >= 12000
    cudaDriverEntryPointQueryResult qr;
    if (cudaGetDriverEntryPoint("cuTensorMapEncodeTiled", &p,
                                cudaEnableDefault, &qr) != cudaSuccess)
        return nullptr;
#else
    if (cudaGetDriverEntryPoint("cuTensorMapEncodeTiled", &p,
                                cudaEnableDefault) != cudaSuccess)
        return nullptr;
#endif
    return (EncodeTiledFn)p;
}

extern "C" void kernel_launch(void* const* d_in, const int* in_sizes, int n_in,
                              void* d_out, int out_size) {
    const float* x_ptr = nullptr;
    const float* t_ptr = nullptr;
    const float* table_ptr = nullptr;
    int N = 0;

    const int TABLE_ELEMS = TIME_RES * N_LEVELS * HASHMAP_SIZE * 4;  // 6,553,600

    for (int i = 0; i < n_in; i++) {
        int s = in_sizes[i];
        if (s == 1)                    t_ptr = (const float*)d_in[i];
        else if (s == TABLE_ELEMS)     table_ptr = (const float*)d_in[i];
        else { x_ptr = (const float*)d_in[i]; N = s / 2; }
    }

    // K1: temporal blend -> g_btable_h (fp16).
    blend_table_kernel<<<(N_LEVELS * HASHMAP_SIZE) / 256, 256>>>(table_ptr, t_ptr);

    // TMA path: out viewed as (8 floats, 4 level-pairs, N points); 32B rows.
    bool tma_ok = false;
    CUtensorMap tmap;
    EncodeTiledFn enc = get_encode_fn();
    if (enc) {
        cuuint64_t dims[3]    = {8, N_LEVELS / 2, (cuuint64_t)N};
        cuuint64_t strides[2] = {32, 128};               // bytes, dims 1..2
        cuuint32_t box[3]     = {8, 1, BOX_ROWS};
        cuuint32_t estr[3]    = {1, 1, 1};
        CUresult r = enc(&tmap, CU_TENSOR_MAP_DATA_TYPE_FLOAT32, 3, d_out,
                         dims, strides, box, estr,
                         CU_TENSOR_MAP_INTERLEAVE_NONE,
                         CU_TENSOR_MAP_SWIZZLE_NONE,
                         CU_TENSOR_MAP_L2_PROMOTION_L2_128B,
                         CU_TENSOR_MAP_FLOAT_OOB_FILL_NONE);
        tma_ok = (r == CUDA_SUCCESS);
    }

    if (tma_ok) {
        // 128 KB table + 2 halves x 3 x 16 KB staging = 224 KB -> 1 CTA/SM.
        const int SMEM = 2 * HASHMAP_SIZE * 8
                       + 2 * NBUF * HTILE * 2 * (int)sizeof(float4);
        cudaFuncSetAttribute(hash_encode_pair_kernel,
                             cudaFuncAttributeMaxDynamicSharedMemorySize, SMEM);
        dim3 grid(37, N_LEVELS / 2);   // 148 CTAs = one wave
        hash_encode_pair_kernel<<<grid, THREADS, SMEM>>>(
            (const float2*)x_ptr, (float4*)d_out, N, tmap);
    } else {
        const int SMEM = 2 * HASHMAP_SIZE * 8;           // 128 KB
        cudaFuncSetAttribute(hash_encode_kernel,
                             cudaFuncAttributeMaxDynamicSharedMemorySize, SMEM);
        dim3 grid(37, N_LEVELS / 2);
        hash_encode_kernel<<<grid, 1024, SMEM>>>(
            (const float2*)x_ptr, (float4*)d_out, N);
    }
}